// round 16
// baseline (speedup 1.0000x reference)
#include <cuda_runtime.h>
#include <cuda_fp16.h>
#include <cstdint>

#define N1i 8192
#define N2i 8192
#define Ci  128
#define HCi 60
#define WCi 80
#define CAPc 3072
#define ZTHR 1.35f

// fp16 operand copies; S stored as order-preserving uint16 keys
__device__ uint32_t g_Ah[N1i * Ci / 2];
__device__ uint32_t g_Bh[N2i * Ci / 2];
__device__ uint16_t g_Sk[(size_t)N1i * N2i];     // 128 MB (keys)
__device__ uint32_t g_Tk[N1i];                   // per-row threshold key16
__device__ float  g_rowPos[N1i];
__device__ float  g_rowNeg[N1i];
__device__ double g_part[32];

#define THR2 130.27274215762787f   // (2*sqrt(32)+0.1)^2

__device__ __forceinline__ uint32_t smem_to_u32(const void* p) {
    uint32_t a;
    asm("{ .reg .u64 t; cvta.to.shared.u64 t, %1; cvt.u32.u64 %0, t; }" : "=r"(a) : "l"(p));
    return a;
}

#define LDSM_X4(r0, r1, r2, r3, addr) \
    asm volatile("ldmatrix.sync.aligned.m8n8.x4.shared.b16 {%0,%1,%2,%3}, [%4];" \
        : "=r"(r0), "=r"(r1), "=r"(r2), "=r"(r3) : "r"(addr))

#define MMAF16(c0, c1, c2, c3, a0, a1, a2, a3, b0, b1) \
    asm volatile("mma.sync.aligned.m16n8k16.row.col.f32.f16.f16.f32 " \
        "{%0,%1,%2,%3}, {%4,%5,%6,%7}, {%8,%9}, {%0,%1,%2,%3};" \
        : "+f"(c0), "+f"(c1), "+f"(c2), "+f"(c3) \
        : "r"(a0), "r"(a1), "r"(a2), "r"(a3), "r"(b0), "r"(b1))

#define CPA16(dst, src) \
    asm volatile("cp.async.cg.shared.global [%0], [%1], 16;" \
        :: "r"(dst), "l"(src) : "memory")
#define CP_COMMIT asm volatile("cp.async.commit_group;" ::: "memory")
#define CP_WAIT1  asm volatile("cp.async.wait_group 1;" ::: "memory")
#define CP_WAIT0  asm volatile("cp.async.wait_group 0;" ::: "memory")

// packed fp16x2 -> order-preserving key16x2
__device__ __forceinline__ uint32_t h2_to_key2(uint32_t w)
{
    uint32_t t = (w >> 15) & 0x00010001u;
    uint32_t xorm = 0x80008000u | (t * 0x7fffu);
    return w ^ xorm;
}
__device__ __forceinline__ float key_to_f(uint32_t k)
{
    uint16_t b = (k & 0x8000u) ? (uint16_t)(k & 0x7fffu) : (uint16_t)(~k);
    return __half2float(__ushort_as_half(b));
}

// ===========================================================================
// Kernel 0: convert fp32 descriptors to fp16 (once per launch)
// ===========================================================================
__global__ void convert_kernel(const float* __restrict__ A, const float* __restrict__ B)
{
    int i = blockIdx.x * 256 + threadIdx.x;
    {
        float4 v = reinterpret_cast<const float4*>(A)[i];
        __half2 h01 = __floats2half2_rn(v.x, v.y);
        __half2 h23 = __floats2half2_rn(v.z, v.w);
        g_Ah[i * 2]     = *reinterpret_cast<uint32_t*>(&h01);
        g_Ah[i * 2 + 1] = *reinterpret_cast<uint32_t*>(&h23);
    }
    {
        float4 v = reinterpret_cast<const float4*>(B)[i];
        __half2 h01 = __floats2half2_rn(v.x, v.y);
        __half2 h23 = __floats2half2_rn(v.z, v.w);
        g_Bh[i * 2]     = *reinterpret_cast<uint32_t*>(&h01);
        g_Bh[i * 2 + 1] = *reinterpret_cast<uint32_t*>(&h23);
    }
}

// ===========================================================================
// Kernel 1: positive hinge + per-row threshold key (one warp per kp)
// ===========================================================================
__global__ void pos_kernel(const float* __restrict__ wkp1,
                           const float* __restrict__ kp1d,
                           const float* __restrict__ desc2)
{
    int gwarp = (blockIdx.x * blockDim.x + threadIdx.x) >> 5;
    int lane  = threadIdx.x & 31;
    if (gwarp >= N1i) return;

    float ky = wkp1[gwarp * 2 + 0];
    float kx = wkp1[gwarp * 2 + 1];
    float py = fminf(fmaxf(ky / 479.0f * 59.0f, 0.0f), 59.0f);
    float px = fminf(fmaxf(kx / 639.0f * 79.0f, 0.0f), 79.0f);
    int y0 = min(max((int)floorf(py), 0), HCi - 2);
    int x0 = min(max((int)floorf(px), 0), WCi - 2);
    float wy = py - (float)y0, wx = px - (float)x0;
    float w00 = (1.0f - wy) * (1.0f - wx);
    float w01 = (1.0f - wy) * wx;
    float w10 = wy * (1.0f - wx);
    float w11 = wy * wx;

    int base = y0 * WCi + x0;
    float s1 = 0.0f, s2 = 0.0f, s3 = 0.0f;
#pragma unroll
    for (int it = 0; it < Ci / 32; ++it) {
        int c = lane + it * 32;
        const float* dp = desc2 + (size_t)c * (HCi * WCi) + base;
        float v = dp[0] * w00 + dp[1] * w01 + dp[WCi] * w10 + dp[WCi + 1] * w11;
        float a = kp1d[(size_t)gwarp * Ci + c];
        s1 = fmaf(v, v, s1);
        s2 = fmaf(v, a, s2);
        s3 = fmaf(a, a, s3);
    }
#pragma unroll
    for (int o = 16; o; o >>= 1) {
        s1 += __shfl_xor_sync(0xffffffffu, s1, o);
        s2 += __shfl_xor_sync(0xffffffffu, s2, o);
        s3 += __shfl_xor_sync(0xffffffffu, s3, o);
    }
    if (lane == 0) {
        float pdot = s2 / fmaxf(sqrtf(s1), 1e-12f);
        g_rowPos[gwarp] = fmaxf(1.0f - pdot, 0.0f);
        float T = ZTHR * sqrtf(s3);
        uint16_t b = __half_as_ushort(__float2half_rn(T));   // T > 0
        g_Tk[gwarp] = (uint32_t)(b | 0x8000u);
    }
}

// ===========================================================================
// Kernel 2: pipelined fp16 GEMM -> key16 S (identical to R8 — fastest measured)
// ===========================================================================
#define RSB 272
#define A_BYTES (128 * RSB)
#define OFF_WKP 0
#define OFF_A   1024
#define OFF_BST (OFF_A + A_BYTES)
#define GEMM_SMEM (OFF_BST + 2 * A_BYTES)

__global__ __launch_bounds__(256, 2)
void gemm_mma_kernel(const float* __restrict__ wkp1,
                     const float* __restrict__ kp2)
{
    extern __shared__ char smem[];
    uint32_t sb = smem_to_u32(smem);
    int tid = threadIdx.x;
    int w   = tid >> 5;
    int l   = tid & 31;
    int bx  = blockIdx.x;
    int row0 = blockIdx.y * 128;

    if (tid < 128) {
        reinterpret_cast<float2*>(smem + OFF_WKP)[tid] =
            reinterpret_cast<const float2*>(wkp1)[row0 + tid];
    }

    const char* pAh = (const char*)g_Ah;
    const char* pBh = (const char*)g_Bh;

#pragma unroll
    for (int it = 0; it < 8; ++it) {
        int id = tid + it * 256;
        int r = id >> 4, ch = id & 15;
        uint32_t dsh = (uint32_t)(r * RSB + ch * 16);
        size_t gso = ((size_t)(row0 + r) * Ci + ch * 8) * 2;
        CPA16(sb + OFF_A + dsh, pAh + gso);
    }
    {
        int col0t = (bx * 8 + 0) * 128;
#pragma unroll
        for (int it = 0; it < 8; ++it) {
            int id = tid + it * 256;
            int r = id >> 4, ch = id & 15;
            uint32_t dsh = (uint32_t)(r * RSB + ch * 16);
            size_t gso = ((size_t)(col0t + r) * Ci + ch * 8) * 2;
            CPA16(sb + OFF_BST + dsh, pBh + gso);
        }
    }
    CP_COMMIT;
    {
        int col0t = (bx * 8 + 1) * 128;
#pragma unroll
        for (int it = 0; it < 8; ++it) {
            int id = tid + it * 256;
            int r = id >> 4, ch = id & 15;
            uint32_t dsh = (uint32_t)(A_BYTES + r * RSB + ch * 16);
            size_t gso = ((size_t)(col0t + r) * Ci + ch * 8) * 2;
            CPA16(sb + OFF_BST + dsh, pBh + gso);
        }
    }
    CP_COMMIT;

    int wm = w & 1, wn = w >> 1;
    int g  = l >> 3, r8 = l & 7;
    uint32_t aoff[4], boff[2];
#pragma unroll
    for (int mt = 0; mt < 4; ++mt) {
        int row = wm * 64 + mt * 16 + (g & 1) * 8 + r8;
        int kof = (g >> 1) * 8;
        aoff[mt] = (uint32_t)(row * RSB + kof * 2);
    }
#pragma unroll
    for (int h = 0; h < 2; ++h) {
        int n = wn * 32 + h * 16 + (g >> 1) * 8 + r8;
        int kof = (g & 1) * 8;
        boff[h] = (uint32_t)(n * RSB + kof * 2);
    }

#pragma unroll 1
    for (int t = 0; t < 8; ++t) {
        if (t < 6) { CP_WAIT1; } else { CP_WAIT0; }
        __syncthreads();

        float c[4][4][4];
#pragma unroll
        for (int mt = 0; mt < 4; ++mt)
#pragma unroll
            for (int nt = 0; nt < 4; ++nt)
#pragma unroll
                for (int q = 0; q < 4; ++q) c[mt][nt][q] = 0.0f;

        uint32_t ab = sb + OFF_A;
        uint32_t bb = sb + OFF_BST + (uint32_t)((t & 1) * A_BYTES);
#pragma unroll
        for (int ks = 0; ks < 8; ++ks) {
            uint32_t k0b = (uint32_t)(ks * 32);
            uint32_t a[16], bfr[8];
#pragma unroll
            for (int mt = 0; mt < 4; ++mt)
                LDSM_X4(a[mt*4], a[mt*4+1], a[mt*4+2], a[mt*4+3], ab + aoff[mt] + k0b);
            LDSM_X4(bfr[0], bfr[1], bfr[2], bfr[3], bb + boff[0] + k0b);
            LDSM_X4(bfr[4], bfr[5], bfr[6], bfr[7], bb + boff[1] + k0b);
#pragma unroll
            for (int mt = 0; mt < 4; ++mt)
#pragma unroll
                for (int nt = 0; nt < 4; ++nt)
                    MMAF16(c[mt][nt][0], c[mt][nt][1], c[mt][nt][2], c[mt][nt][3],
                           a[mt*4], a[mt*4+1], a[mt*4+2], a[mt*4+3],
                           bfr[nt*2], bfr[nt*2+1]);
        }

        int col0t = (bx * 8 + t) * 128;
        const float2* wks = reinterpret_cast<const float2*>(smem + OFF_WKP);
#pragma unroll
        for (int mt = 0; mt < 4; ++mt) {
            int rloc = wm * 64 + mt * 16 + (l >> 2);
            int rA = row0 + rloc;
            float2 wpA = wks[rloc];
            float2 wpB = wks[rloc + 8];
#pragma unroll
            for (int nt = 0; nt < 4; ++nt) {
                int ctg = col0t + wn * 32 + nt * 8 + 2 * (l & 3);
                float2 p0 = reinterpret_cast<const float2*>(kp2)[ctg];
                float2 p1 = reinterpret_cast<const float2*>(kp2)[ctg + 1];
                float v0 = c[mt][nt][0], v1 = c[mt][nt][1];
                float v2 = c[mt][nt][2], v3 = c[mt][nt][3];
                float dy = wpA.x - p0.x, dx = wpA.y - p0.y;
                if (fmaf(dy, dy, dx * dx) <= THR2) v0 -= 5.0f;
                dy = wpA.x - p1.x; dx = wpA.y - p1.y;
                if (fmaf(dy, dy, dx * dx) <= THR2) v1 -= 5.0f;
                dy = wpB.x - p0.x; dx = wpB.y - p0.y;
                if (fmaf(dy, dy, dx * dx) <= THR2) v2 -= 5.0f;
                dy = wpB.x - p1.x; dx = wpB.y - p1.y;
                if (fmaf(dy, dy, dx * dx) <= THR2) v3 -= 5.0f;
                __half2 h01 = __floats2half2_rn(v0, v1);
                __half2 h23 = __floats2half2_rn(v2, v3);
                size_t base0 = (size_t)rA * N2i + ctg;
                *reinterpret_cast<uint32_t*>(g_Sk + base0) =
                    h2_to_key2(*reinterpret_cast<uint32_t*>(&h01));
                *reinterpret_cast<uint32_t*>(g_Sk + base0 + 8 * N2i) =
                    h2_to_key2(*reinterpret_cast<uint32_t*>(&h23));
            }
        }
        __syncthreads();

        if (t + 2 < 8) {
            int col0n = (bx * 8 + t + 2) * 128;
            uint32_t dstb = sb + OFF_BST + (uint32_t)((t & 1) * A_BYTES);
#pragma unroll
            for (int it = 0; it < 8; ++it) {
                int id = tid + it * 256;
                int r = id >> 4, ch = id & 15;
                uint32_t dsh = (uint32_t)(r * RSB + ch * 16);
                size_t gso = ((size_t)(col0n + r) * Ci + ch * 8) * 2;
                CPA16(dstb + dsh, pBh + gso);
            }
            CP_COMMIT;
        }
    }
}

// ===========================================================================
// Kernel 3: fused filter (SIMD threshold) + exact select on candidates.
// 512 threads; 8 u32 per thread (2x uint4); smem candidate buffer.
// ===========================================================================
__device__ __forceinline__ void sel256(volatile uint32_t* hist, int target,
                                       int tid, int lane, int wid, int* s_w,
                                       volatile uint32_t* s_bin, volatile int* s_above)
{
    int hv = (tid < 256) ? (int)hist[255 - tid] : 0;
    int x = hv;
#pragma unroll
    for (int o = 1; o < 32; o <<= 1) {
        int t2 = __shfl_up_sync(0xffffffffu, x, o);
        if (lane >= o) x += t2;
    }
    if (lane == 31 && wid < 8) s_w[wid] = x;
    __syncthreads();
    if (tid == 0) {
        int run = 0;
#pragma unroll
        for (int i = 0; i < 8; ++i) { int t2 = s_w[i]; s_w[i] = run; run += t2; }
    }
    __syncthreads();
    if (tid < 256) {
        int incl = s_w[wid] + x;
        int excl = incl - hv;
        if (hv > 0 && excl < target && incl >= target) {
            *s_bin = (uint32_t)(255 - tid);
            *s_above = excl;
        }
    }
    __syncthreads();
}

__global__ __launch_bounds__(512)
void select_kernel()
{
    __shared__ uint32_t sbuf[CAPc];
    __shared__ uint32_t hist[256];
    __shared__ int s_w[8];
    __shared__ uint32_t s_bin;
    __shared__ int s_above;
    __shared__ int s_n;
    __shared__ float red[512];

    int row = blockIdx.x;
    int tid = threadIdx.x;
    int lane = tid & 31;
    int wid  = tid >> 5;

    if (tid == 0) s_n = 0;
    if (tid < 256) hist[tid] = 0;
    __syncthreads();

    uint32_t Tk = g_Tk[row];
    uint32_t TT = Tk | (Tk << 16);
    const uint4* rowp = reinterpret_cast<const uint4*>(g_Sk + (size_t)row * N2i);

    // ---- filter pass: 2 uint4 per thread ----
#pragma unroll
    for (int it = 0; it < 2; ++it) {
        uint4 v = rowp[tid + it * 512];
        uint32_t ws[4] = {v.x, v.y, v.z, v.w};
#pragma unroll
        for (int q = 0; q < 4; ++q) {
            uint32_t m = __vcmpgeu2(ws[q], TT);
            if (m) {
                if (m & 0xffffu) { int p = atomicAdd(&s_n, 1); if (p < CAPc) sbuf[p] = ws[q] & 0xffffu; }
                if (m >> 16)     { int p = atomicAdd(&s_n, 1); if (p < CAPc) sbuf[p] = ws[q] >> 16; }
            }
        }
    }
    __syncthreads();
    int n = s_n;
    float partial = 0.0f;

    if (n >= 256 && n <= CAPc) {
        // ---- exact 2-level (8/8-bit) select on candidates ----
        for (int i = tid; i < n; i += 512)
            atomicAdd(&hist[sbuf[i] >> 8], 1u);
        __syncthreads();
        sel256(hist, 256, tid, lane, wid, s_w, &s_bin, &s_above);
        uint32_t b1 = s_bin;
        int target2 = 256 - s_above;
        __syncthreads();
        if (tid < 256) hist[tid] = 0;
        __syncthreads();
        for (int i = tid; i < n; i += 512) {
            uint32_t k = sbuf[i];
            uint32_t d = k >> 8;
            if (d > b1) partial += fmaxf(key_to_f(k) - 0.2f, 0.0f);
            else if (d == b1) atomicAdd(&hist[k & 255u], 1u);
        }
        __syncthreads();
        sel256(hist, target2, tid, lane, wid, s_w, &s_bin, &s_above);
        uint32_t b2 = s_bin;
        int remaining = target2 - s_above;
        for (int i = tid; i < n; i += 512) {
            uint32_t k = sbuf[i];
            if ((k >> 8) == b1 && (k & 255u) > b2)
                partial += fmaxf(key_to_f(k) - 0.2f, 0.0f);
        }
        if (tid == 0)
            partial += (float)remaining * fmaxf(key_to_f((b1 << 8) | b2) - 0.2f, 0.0f);
    } else {
        // ---- fallback: exact full-row 2-level select from global (rare) ----
        __syncthreads();
        if (tid < 256) hist[tid] = 0;
        __syncthreads();
        const uint32_t* rp = reinterpret_cast<const uint32_t*>(g_Sk + (size_t)row * N2i);
        for (int i = tid; i < N2i / 2; i += 512) {
            uint32_t wv = rp[i];
            atomicAdd(&hist[(wv >> 8) & 0xffu], 1u);
            atomicAdd(&hist[wv >> 24], 1u);
        }
        __syncthreads();
        sel256(hist, 256, tid, lane, wid, s_w, &s_bin, &s_above);
        uint32_t b1 = s_bin;
        int target2 = 256 - s_above;
        __syncthreads();
        if (tid < 256) hist[tid] = 0;
        __syncthreads();
        for (int i = tid; i < N2i / 2; i += 512) {
            uint32_t wv = rp[i];
            uint32_t lo = wv & 0xffffu, hi = wv >> 16;
            if ((lo >> 8) > b1) partial += fmaxf(key_to_f(lo) - 0.2f, 0.0f);
            else if ((lo >> 8) == b1) atomicAdd(&hist[lo & 255u], 1u);
            if ((hi >> 8) > b1) partial += fmaxf(key_to_f(hi) - 0.2f, 0.0f);
            else if ((hi >> 8) == b1) atomicAdd(&hist[hi & 255u], 1u);
        }
        __syncthreads();
        sel256(hist, target2, tid, lane, wid, s_w, &s_bin, &s_above);
        uint32_t b2 = s_bin;
        int remaining = target2 - s_above;
        for (int i = tid; i < N2i / 2; i += 512) {
            uint32_t wv = rp[i];
            uint32_t lo = wv & 0xffffu, hi = wv >> 16;
            if ((lo >> 8) == b1 && (lo & 255u) > b2) partial += fmaxf(key_to_f(lo) - 0.2f, 0.0f);
            if ((hi >> 8) == b1 && (hi & 255u) > b2) partial += fmaxf(key_to_f(hi) - 0.2f, 0.0f);
        }
        if (tid == 0)
            partial += (float)remaining * fmaxf(key_to_f((b1 << 8) | b2) - 0.2f, 0.0f);
    }

    red[tid] = partial;
    __syncthreads();
#pragma unroll
    for (int s = 256; s; s >>= 1) {
        if (tid < s) red[tid] += red[tid + s];
        __syncthreads();
    }
    if (tid == 0) g_rowNeg[row] = red[0];
}

// ===========================================================================
// Kernels 4/5: two-stage deterministic final reduction
// ===========================================================================
__global__ void final1_kernel()
{
    __shared__ double red[256];
    int b = blockIdx.x, tid = threadIdx.x;
    int i = b * 256 + tid;
    const double balance = 256.0 / 3.0;
    red[tid] = (double)g_rowPos[i] * balance + (double)g_rowNeg[i];
    __syncthreads();
#pragma unroll
    for (int st = 128; st; st >>= 1) {
        if (tid < st) red[tid] += red[tid + st];
        __syncthreads();
    }
    if (tid == 0) g_part[b] = red[0];
}

__global__ void final2_kernel(float* __restrict__ out)
{
    if (threadIdx.x == 0) {
        double s = 0.0;
        for (int i = 0; i < 32; ++i) s += g_part[i];
        out[0] = (float)(s * (1.0 / ((double)N1i * 256.0)));
    }
}

// ===========================================================================
extern "C" void kernel_launch(void* const* d_in, const int* in_sizes, int n_in,
                              void* d_out, int out_size)
{
    (void)in_sizes; (void)n_in; (void)out_size;
    const float* wkp1  = (const float*)d_in[1];
    const float* kp2   = (const float*)d_in[2];
    const float* kp1d  = (const float*)d_in[3];
    const float* kp2d  = (const float*)d_in[4];
    const float* desc2 = (const float*)d_in[5];
    float* out = (float*)d_out;

    cudaFuncSetAttribute(gemm_mma_kernel,
                         cudaFuncAttributeMaxDynamicSharedMemorySize, GEMM_SMEM);

    convert_kernel<<<1024, 256>>>(kp1d, kp2d);
    pos_kernel<<<N1i / 8, 256>>>(wkp1, kp1d, desc2);

    dim3 grid(8, 64);
    gemm_mma_kernel<<<grid, 256, GEMM_SMEM>>>(wkp1, kp2);

    select_kernel<<<N1i, 512>>>();

    final1_kernel<<<32, 256>>>();
    final2_kernel<<<1, 32>>>(out);
}

// round 17
// speedup vs baseline: 1.0025x; 1.0025x over previous
#include <cuda_runtime.h>
#include <cuda_fp16.h>
#include <cstdint>

#define N1i 8192
#define N2i 8192
#define Ci  128
#define HCi 60
#define WCi 80
#define CAPc 3072
#define ZTHR 1.35f

// fp16 operand copies; S stored as order-preserving uint16 keys
__device__ uint32_t g_Ah[N1i * Ci / 2];
__device__ uint32_t g_Bh[N2i * Ci / 2];
__device__ uint16_t g_Sk[(size_t)N1i * N2i];     // 128 MB (keys)
__device__ uint32_t g_Tk[N1i];                   // per-row threshold key16
__device__ float  g_rowPos[N1i];
__device__ float  g_rowNeg[N1i];
__device__ double g_part[32];

#define THR2 130.27274215762787f   // (2*sqrt(32)+0.1)^2

__device__ __forceinline__ uint32_t smem_to_u32(const void* p) {
    uint32_t a;
    asm("{ .reg .u64 t; cvta.to.shared.u64 t, %1; cvt.u32.u64 %0, t; }" : "=r"(a) : "l"(p));
    return a;
}

#define LDSM_X4(r0, r1, r2, r3, addr) \
    asm volatile("ldmatrix.sync.aligned.m8n8.x4.shared.b16 {%0,%1,%2,%3}, [%4];" \
        : "=r"(r0), "=r"(r1), "=r"(r2), "=r"(r3) : "r"(addr))

#define MMAF16(c0, c1, c2, c3, a0, a1, a2, a3, b0, b1) \
    asm volatile("mma.sync.aligned.m16n8k16.row.col.f32.f16.f16.f32 " \
        "{%0,%1,%2,%3}, {%4,%5,%6,%7}, {%8,%9}, {%0,%1,%2,%3};" \
        : "+f"(c0), "+f"(c1), "+f"(c2), "+f"(c3) \
        : "r"(a0), "r"(a1), "r"(a2), "r"(a3), "r"(b0), "r"(b1))

#define CPA16(dst, src) \
    asm volatile("cp.async.cg.shared.global [%0], [%1], 16;" \
        :: "r"(dst), "l"(src) : "memory")
#define CP_COMMIT asm volatile("cp.async.commit_group;" ::: "memory")
#define CP_WAIT1  asm volatile("cp.async.wait_group 1;" ::: "memory")
#define CP_WAIT0  asm volatile("cp.async.wait_group 0;" ::: "memory")

// packed fp16x2 -> order-preserving key16x2
__device__ __forceinline__ uint32_t h2_to_key2(uint32_t w)
{
    uint32_t t = (w >> 15) & 0x00010001u;
    uint32_t xorm = 0x80008000u | (t * 0x7fffu);
    return w ^ xorm;
}
__device__ __forceinline__ float key_to_f(uint32_t k)
{
    uint16_t b = (k & 0x8000u) ? (uint16_t)(k & 0x7fffu) : (uint16_t)(~k);
    return __half2float(__ushort_as_half(b));
}

// ===========================================================================
// Kernel 0: convert fp32 descriptors to fp16 (once per launch)
// ===========================================================================
__global__ void convert_kernel(const float* __restrict__ A, const float* __restrict__ B)
{
    int i = blockIdx.x * 256 + threadIdx.x;
    {
        float4 v = reinterpret_cast<const float4*>(A)[i];
        __half2 h01 = __floats2half2_rn(v.x, v.y);
        __half2 h23 = __floats2half2_rn(v.z, v.w);
        g_Ah[i * 2]     = *reinterpret_cast<uint32_t*>(&h01);
        g_Ah[i * 2 + 1] = *reinterpret_cast<uint32_t*>(&h23);
    }
    {
        float4 v = reinterpret_cast<const float4*>(B)[i];
        __half2 h01 = __floats2half2_rn(v.x, v.y);
        __half2 h23 = __floats2half2_rn(v.z, v.w);
        g_Bh[i * 2]     = *reinterpret_cast<uint32_t*>(&h01);
        g_Bh[i * 2 + 1] = *reinterpret_cast<uint32_t*>(&h23);
    }
}

// ===========================================================================
// Kernel 1: positive hinge + per-row threshold key (one warp per kp)
// ===========================================================================
__global__ void pos_kernel(const float* __restrict__ wkp1,
                           const float* __restrict__ kp1d,
                           const float* __restrict__ desc2)
{
    int gwarp = (blockIdx.x * blockDim.x + threadIdx.x) >> 5;
    int lane  = threadIdx.x & 31;
    if (gwarp >= N1i) return;

    float ky = wkp1[gwarp * 2 + 0];
    float kx = wkp1[gwarp * 2 + 1];
    float py = fminf(fmaxf(ky / 479.0f * 59.0f, 0.0f), 59.0f);
    float px = fminf(fmaxf(kx / 639.0f * 79.0f, 0.0f), 79.0f);
    int y0 = min(max((int)floorf(py), 0), HCi - 2);
    int x0 = min(max((int)floorf(px), 0), WCi - 2);
    float wy = py - (float)y0, wx = px - (float)x0;
    float w00 = (1.0f - wy) * (1.0f - wx);
    float w01 = (1.0f - wy) * wx;
    float w10 = wy * (1.0f - wx);
    float w11 = wy * wx;

    int base = y0 * WCi + x0;
    float s1 = 0.0f, s2 = 0.0f, s3 = 0.0f;
#pragma unroll
    for (int it = 0; it < Ci / 32; ++it) {
        int c = lane + it * 32;
        const float* dp = desc2 + (size_t)c * (HCi * WCi) + base;
        float v = dp[0] * w00 + dp[1] * w01 + dp[WCi] * w10 + dp[WCi + 1] * w11;
        float a = kp1d[(size_t)gwarp * Ci + c];
        s1 = fmaf(v, v, s1);
        s2 = fmaf(v, a, s2);
        s3 = fmaf(a, a, s3);
    }
#pragma unroll
    for (int o = 16; o; o >>= 1) {
        s1 += __shfl_xor_sync(0xffffffffu, s1, o);
        s2 += __shfl_xor_sync(0xffffffffu, s2, o);
        s3 += __shfl_xor_sync(0xffffffffu, s3, o);
    }
    if (lane == 0) {
        float pdot = s2 / fmaxf(sqrtf(s1), 1e-12f);
        g_rowPos[gwarp] = fmaxf(1.0f - pdot, 0.0f);
        float T = ZTHR * sqrtf(s3);
        uint16_t b = __half_as_ushort(__float2half_rn(T));   // T > 0
        g_Tk[gwarp] = (uint32_t)(b | 0x8000u);
    }
}

// ===========================================================================
// Kernel 2: pipelined fp16 GEMM -> key16 S (identical to R8 — fastest measured)
// ===========================================================================
#define RSB 272
#define A_BYTES (128 * RSB)
#define OFF_WKP 0
#define OFF_A   1024
#define OFF_BST (OFF_A + A_BYTES)
#define GEMM_SMEM (OFF_BST + 2 * A_BYTES)

__global__ __launch_bounds__(256, 2)
void gemm_mma_kernel(const float* __restrict__ wkp1,
                     const float* __restrict__ kp2)
{
    extern __shared__ char smem[];
    uint32_t sb = smem_to_u32(smem);
    int tid = threadIdx.x;
    int w   = tid >> 5;
    int l   = tid & 31;
    int bx  = blockIdx.x;
    int row0 = blockIdx.y * 128;

    if (tid < 128) {
        reinterpret_cast<float2*>(smem + OFF_WKP)[tid] =
            reinterpret_cast<const float2*>(wkp1)[row0 + tid];
    }

    const char* pAh = (const char*)g_Ah;
    const char* pBh = (const char*)g_Bh;

#pragma unroll
    for (int it = 0; it < 8; ++it) {
        int id = tid + it * 256;
        int r = id >> 4, ch = id & 15;
        uint32_t dsh = (uint32_t)(r * RSB + ch * 16);
        size_t gso = ((size_t)(row0 + r) * Ci + ch * 8) * 2;
        CPA16(sb + OFF_A + dsh, pAh + gso);
    }
    {
        int col0t = (bx * 8 + 0) * 128;
#pragma unroll
        for (int it = 0; it < 8; ++it) {
            int id = tid + it * 256;
            int r = id >> 4, ch = id & 15;
            uint32_t dsh = (uint32_t)(r * RSB + ch * 16);
            size_t gso = ((size_t)(col0t + r) * Ci + ch * 8) * 2;
            CPA16(sb + OFF_BST + dsh, pBh + gso);
        }
    }
    CP_COMMIT;
    {
        int col0t = (bx * 8 + 1) * 128;
#pragma unroll
        for (int it = 0; it < 8; ++it) {
            int id = tid + it * 256;
            int r = id >> 4, ch = id & 15;
            uint32_t dsh = (uint32_t)(A_BYTES + r * RSB + ch * 16);
            size_t gso = ((size_t)(col0t + r) * Ci + ch * 8) * 2;
            CPA16(sb + OFF_BST + dsh, pBh + gso);
        }
    }
    CP_COMMIT;

    int wm = w & 1, wn = w >> 1;
    int g  = l >> 3, r8 = l & 7;
    uint32_t aoff[4], boff[2];
#pragma unroll
    for (int mt = 0; mt < 4; ++mt) {
        int row = wm * 64 + mt * 16 + (g & 1) * 8 + r8;
        int kof = (g >> 1) * 8;
        aoff[mt] = (uint32_t)(row * RSB + kof * 2);
    }
#pragma unroll
    for (int h = 0; h < 2; ++h) {
        int n = wn * 32 + h * 16 + (g >> 1) * 8 + r8;
        int kof = (g & 1) * 8;
        boff[h] = (uint32_t)(n * RSB + kof * 2);
    }

#pragma unroll 1
    for (int t = 0; t < 8; ++t) {
        if (t < 6) { CP_WAIT1; } else { CP_WAIT0; }
        __syncthreads();

        float c[4][4][4];
#pragma unroll
        for (int mt = 0; mt < 4; ++mt)
#pragma unroll
            for (int nt = 0; nt < 4; ++nt)
#pragma unroll
                for (int q = 0; q < 4; ++q) c[mt][nt][q] = 0.0f;

        uint32_t ab = sb + OFF_A;
        uint32_t bb = sb + OFF_BST + (uint32_t)((t & 1) * A_BYTES);
#pragma unroll
        for (int ks = 0; ks < 8; ++ks) {
            uint32_t k0b = (uint32_t)(ks * 32);
            uint32_t a[16], bfr[8];
#pragma unroll
            for (int mt = 0; mt < 4; ++mt)
                LDSM_X4(a[mt*4], a[mt*4+1], a[mt*4+2], a[mt*4+3], ab + aoff[mt] + k0b);
            LDSM_X4(bfr[0], bfr[1], bfr[2], bfr[3], bb + boff[0] + k0b);
            LDSM_X4(bfr[4], bfr[5], bfr[6], bfr[7], bb + boff[1] + k0b);
#pragma unroll
            for (int mt = 0; mt < 4; ++mt)
#pragma unroll
                for (int nt = 0; nt < 4; ++nt)
                    MMAF16(c[mt][nt][0], c[mt][nt][1], c[mt][nt][2], c[mt][nt][3],
                           a[mt*4], a[mt*4+1], a[mt*4+2], a[mt*4+3],
                           bfr[nt*2], bfr[nt*2+1]);
        }

        int col0t = (bx * 8 + t) * 128;
        const float2* wks = reinterpret_cast<const float2*>(smem + OFF_WKP);
#pragma unroll
        for (int mt = 0; mt < 4; ++mt) {
            int rloc = wm * 64 + mt * 16 + (l >> 2);
            int rA = row0 + rloc;
            float2 wpA = wks[rloc];
            float2 wpB = wks[rloc + 8];
#pragma unroll
            for (int nt = 0; nt < 4; ++nt) {
                int ctg = col0t + wn * 32 + nt * 8 + 2 * (l & 3);
                float2 p0 = reinterpret_cast<const float2*>(kp2)[ctg];
                float2 p1 = reinterpret_cast<const float2*>(kp2)[ctg + 1];
                float v0 = c[mt][nt][0], v1 = c[mt][nt][1];
                float v2 = c[mt][nt][2], v3 = c[mt][nt][3];
                float dy = wpA.x - p0.x, dx = wpA.y - p0.y;
                if (fmaf(dy, dy, dx * dx) <= THR2) v0 -= 5.0f;
                dy = wpA.x - p1.x; dx = wpA.y - p1.y;
                if (fmaf(dy, dy, dx * dx) <= THR2) v1 -= 5.0f;
                dy = wpB.x - p0.x; dx = wpB.y - p0.y;
                if (fmaf(dy, dy, dx * dx) <= THR2) v2 -= 5.0f;
                dy = wpB.x - p1.x; dx = wpB.y - p1.y;
                if (fmaf(dy, dy, dx * dx) <= THR2) v3 -= 5.0f;
                __half2 h01 = __floats2half2_rn(v0, v1);
                __half2 h23 = __floats2half2_rn(v2, v3);
                size_t base0 = (size_t)rA * N2i + ctg;
                *reinterpret_cast<uint32_t*>(g_Sk + base0) =
                    h2_to_key2(*reinterpret_cast<uint32_t*>(&h01));
                *reinterpret_cast<uint32_t*>(g_Sk + base0 + 8 * N2i) =
                    h2_to_key2(*reinterpret_cast<uint32_t*>(&h23));
            }
        }
        __syncthreads();

        if (t + 2 < 8) {
            int col0n = (bx * 8 + t + 2) * 128;
            uint32_t dstb = sb + OFF_BST + (uint32_t)((t & 1) * A_BYTES);
#pragma unroll
            for (int it = 0; it < 8; ++it) {
                int id = tid + it * 256;
                int r = id >> 4, ch = id & 15;
                uint32_t dsh = (uint32_t)(r * RSB + ch * 16);
                size_t gso = ((size_t)(col0n + r) * Ci + ch * 8) * 2;
                CPA16(dstb + dsh, pBh + gso);
            }
            CP_COMMIT;
        }
    }
}

// ===========================================================================
// Kernel 3: fused filter (SIMD threshold) + exact select on candidates.
// 512 threads; 8 u32 per thread (2x uint4); smem candidate buffer.
// ===========================================================================
__device__ __forceinline__ void sel256(volatile uint32_t* hist, int target,
                                       int tid, int lane, int wid, int* s_w,
                                       volatile uint32_t* s_bin, volatile int* s_above)
{
    int hv = (tid < 256) ? (int)hist[255 - tid] : 0;
    int x = hv;
#pragma unroll
    for (int o = 1; o < 32; o <<= 1) {
        int t2 = __shfl_up_sync(0xffffffffu, x, o);
        if (lane >= o) x += t2;
    }
    if (lane == 31 && wid < 8) s_w[wid] = x;
    __syncthreads();
    if (tid == 0) {
        int run = 0;
#pragma unroll
        for (int i = 0; i < 8; ++i) { int t2 = s_w[i]; s_w[i] = run; run += t2; }
    }
    __syncthreads();
    if (tid < 256) {
        int incl = s_w[wid] + x;
        int excl = incl - hv;
        if (hv > 0 && excl < target && incl >= target) {
            *s_bin = (uint32_t)(255 - tid);
            *s_above = excl;
        }
    }
    __syncthreads();
}

__global__ __launch_bounds__(512)
void select_kernel()
{
    __shared__ uint32_t sbuf[CAPc];
    __shared__ uint32_t hist[256];
    __shared__ int s_w[8];
    __shared__ uint32_t s_bin;
    __shared__ int s_above;
    __shared__ int s_n;
    __shared__ float red[512];

    int row = blockIdx.x;
    int tid = threadIdx.x;
    int lane = tid & 31;
    int wid  = tid >> 5;

    if (tid == 0) s_n = 0;
    if (tid < 256) hist[tid] = 0;
    __syncthreads();

    uint32_t Tk = g_Tk[row];
    uint32_t TT = Tk | (Tk << 16);
    const uint4* rowp = reinterpret_cast<const uint4*>(g_Sk + (size_t)row * N2i);

    // ---- filter pass: 2 uint4 per thread ----
#pragma unroll
    for (int it = 0; it < 2; ++it) {
        uint4 v = rowp[tid + it * 512];
        uint32_t ws[4] = {v.x, v.y, v.z, v.w};
#pragma unroll
        for (int q = 0; q < 4; ++q) {
            uint32_t m = __vcmpgeu2(ws[q], TT);
            if (m) {
                if (m & 0xffffu) { int p = atomicAdd(&s_n, 1); if (p < CAPc) sbuf[p] = ws[q] & 0xffffu; }
                if (m >> 16)     { int p = atomicAdd(&s_n, 1); if (p < CAPc) sbuf[p] = ws[q] >> 16; }
            }
        }
    }
    __syncthreads();
    int n = s_n;
    float partial = 0.0f;

    if (n >= 256 && n <= CAPc) {
        // ---- exact 2-level (8/8-bit) select on candidates ----
        for (int i = tid; i < n; i += 512)
            atomicAdd(&hist[sbuf[i] >> 8], 1u);
        __syncthreads();
        sel256(hist, 256, tid, lane, wid, s_w, &s_bin, &s_above);
        uint32_t b1 = s_bin;
        int target2 = 256 - s_above;
        __syncthreads();
        if (tid < 256) hist[tid] = 0;
        __syncthreads();
        for (int i = tid; i < n; i += 512) {
            uint32_t k = sbuf[i];
            uint32_t d = k >> 8;
            if (d > b1) partial += fmaxf(key_to_f(k) - 0.2f, 0.0f);
            else if (d == b1) atomicAdd(&hist[k & 255u], 1u);
        }
        __syncthreads();
        sel256(hist, target2, tid, lane, wid, s_w, &s_bin, &s_above);
        uint32_t b2 = s_bin;
        int remaining = target2 - s_above;
        for (int i = tid; i < n; i += 512) {
            uint32_t k = sbuf[i];
            if ((k >> 8) == b1 && (k & 255u) > b2)
                partial += fmaxf(key_to_f(k) - 0.2f, 0.0f);
        }
        if (tid == 0)
            partial += (float)remaining * fmaxf(key_to_f((b1 << 8) | b2) - 0.2f, 0.0f);
    } else {
        // ---- fallback: exact full-row 2-level select from global (rare) ----
        __syncthreads();
        if (tid < 256) hist[tid] = 0;
        __syncthreads();
        const uint32_t* rp = reinterpret_cast<const uint32_t*>(g_Sk + (size_t)row * N2i);
        for (int i = tid; i < N2i / 2; i += 512) {
            uint32_t wv = rp[i];
            atomicAdd(&hist[(wv >> 8) & 0xffu], 1u);
            atomicAdd(&hist[wv >> 24], 1u);
        }
        __syncthreads();
        sel256(hist, 256, tid, lane, wid, s_w, &s_bin, &s_above);
        uint32_t b1 = s_bin;
        int target2 = 256 - s_above;
        __syncthreads();
        if (tid < 256) hist[tid] = 0;
        __syncthreads();
        for (int i = tid; i < N2i / 2; i += 512) {
            uint32_t wv = rp[i];
            uint32_t lo = wv & 0xffffu, hi = wv >> 16;
            if ((lo >> 8) > b1) partial += fmaxf(key_to_f(lo) - 0.2f, 0.0f);
            else if ((lo >> 8) == b1) atomicAdd(&hist[lo & 255u], 1u);
            if ((hi >> 8) > b1) partial += fmaxf(key_to_f(hi) - 0.2f, 0.0f);
            else if ((hi >> 8) == b1) atomicAdd(&hist[hi & 255u], 1u);
        }
        __syncthreads();
        sel256(hist, target2, tid, lane, wid, s_w, &s_bin, &s_above);
        uint32_t b2 = s_bin;
        int remaining = target2 - s_above;
        for (int i = tid; i < N2i / 2; i += 512) {
            uint32_t wv = rp[i];
            uint32_t lo = wv & 0xffffu, hi = wv >> 16;
            if ((lo >> 8) == b1 && (lo & 255u) > b2) partial += fmaxf(key_to_f(lo) - 0.2f, 0.0f);
            if ((hi >> 8) == b1 && (hi & 255u) > b2) partial += fmaxf(key_to_f(hi) - 0.2f, 0.0f);
        }
        if (tid == 0)
            partial += (float)remaining * fmaxf(key_to_f((b1 << 8) | b2) - 0.2f, 0.0f);
    }

    red[tid] = partial;
    __syncthreads();
#pragma unroll
    for (int s = 256; s; s >>= 1) {
        if (tid < s) red[tid] += red[tid + s];
        __syncthreads();
    }
    if (tid == 0) g_rowNeg[row] = red[0];
}

// ===========================================================================
// Kernels 4/5: two-stage deterministic final reduction
// ===========================================================================
__global__ void final1_kernel()
{
    __shared__ double red[256];
    int b = blockIdx.x, tid = threadIdx.x;
    int i = b * 256 + tid;
    const double balance = 256.0 / 3.0;
    red[tid] = (double)g_rowPos[i] * balance + (double)g_rowNeg[i];
    __syncthreads();
#pragma unroll
    for (int st = 128; st; st >>= 1) {
        if (tid < st) red[tid] += red[tid + st];
        __syncthreads();
    }
    if (tid == 0) g_part[b] = red[0];
}

__global__ void final2_kernel(float* __restrict__ out)
{
    if (threadIdx.x == 0) {
        double s = 0.0;
        for (int i = 0; i < 32; ++i) s += g_part[i];
        out[0] = (float)(s * (1.0 / ((double)N1i * 256.0)));
    }
}

// ===========================================================================
extern "C" void kernel_launch(void* const* d_in, const int* in_sizes, int n_in,
                              void* d_out, int out_size)
{
    (void)in_sizes; (void)n_in; (void)out_size;
    const float* wkp1  = (const float*)d_in[1];
    const float* kp2   = (const float*)d_in[2];
    const float* kp1d  = (const float*)d_in[3];
    const float* kp2d  = (const float*)d_in[4];
    const float* desc2 = (const float*)d_in[5];
    float* out = (float*)d_out;

    cudaFuncSetAttribute(gemm_mma_kernel,
                         cudaFuncAttributeMaxDynamicSharedMemorySize, GEMM_SMEM);

    convert_kernel<<<1024, 256>>>(kp1d, kp2d);
    pos_kernel<<<N1i / 8, 256>>>(wkp1, kp1d, desc2);

    dim3 grid(8, 64);
    gemm_mma_kernel<<<grid, 256, GEMM_SMEM>>>(wkp1, kp2);

    select_kernel<<<N1i, 512>>>();

    final1_kernel<<<32, 256>>>();
    final2_kernel<<<1, 32>>>(out);
}